// round 5
// baseline (speedup 1.0000x reference)
#include <cuda_runtime.h>
#include <cuda_bf16.h>

// Problem constants
#define BB   2
#define SS   1024
#define HID  2048
#define NH   32
#define NKV  4
#define DH   128
#define QKV_N 5120          // (32 + 2*4) * 128
#define CTX_N 4096          // 32 * 128
#define NTOK  2048          // B*S
#define ATT_SCALE 0.08838834764831845f   // 1/sqrt(128)
#define EPS  1e-6f

// Scratch (no cudaMalloc allowed): qkv projection output + attention context
__device__ float g_qkv[NTOK * QKV_N];   // 40 MiB
__device__ float g_ctx[NTOK * CTX_N];   // 32 MiB

// ---------------------------------------------------------------------------
// SGEMM: C[M,N] = A[M,K] @ B[K,N], all row-major, fp32.
// 128x128 block tile, BK=8, 256 threads, 8x8 microtile, register prefetch.
// Requires M%128==0, N%128==0, K%8==0 (true for all three uses).
// ---------------------------------------------------------------------------
__global__ __launch_bounds__(256) void sgemm128(const float* __restrict__ A,
                                                const float* __restrict__ B,
                                                float* __restrict__ C,
                                                int M, int N, int K) {
    __shared__ float As[8 * 128];
    __shared__ float Bs[8 * 128];
    const int t  = threadIdx.x;
    const int tx = t & 15, ty = t >> 4;
    const int arow = t >> 1, ak4 = (t & 1) << 2;   // A tile: 128 rows x 8 k
    const int brow = t >> 5, bc4 = (t & 31) << 2;  // B tile: 8 rows x 128 cols

    const float* Ab = A + (blockIdx.y * 128 + arow) * K + ak4;
    const float* Bb = B + brow * N + blockIdx.x * 128 + bc4;

    float acc[8][8];
#pragma unroll
    for (int i = 0; i < 8; i++)
#pragma unroll
        for (int j = 0; j < 8; j++) acc[i][j] = 0.f;

    float4 a = *(const float4*)Ab;
    float4 b = *(const float4*)Bb;

    for (int k0 = 0; k0 < K; k0 += 8) {
        As[(ak4 + 0) * 128 + arow] = a.x;
        As[(ak4 + 1) * 128 + arow] = a.y;
        As[(ak4 + 2) * 128 + arow] = a.z;
        As[(ak4 + 3) * 128 + arow] = a.w;
        *(float4*)&Bs[brow * 128 + bc4] = b;
        __syncthreads();

        if (k0 + 8 < K) {   // prefetch next tile while computing this one
            a = *(const float4*)(Ab + k0 + 8);
            b = *(const float4*)(Bb + (k0 + 8) * N);
        }

#pragma unroll
        for (int k = 0; k < 8; ++k) {
            float ar[8], br[8];
            *(float4*)(ar)     = *(float4*)&As[k * 128 + ty * 8];
            *(float4*)(ar + 4) = *(float4*)&As[k * 128 + ty * 8 + 4];
            *(float4*)(br)     = *(float4*)&Bs[k * 128 + tx * 8];
            *(float4*)(br + 4) = *(float4*)&Bs[k * 128 + tx * 8 + 4];
#pragma unroll
            for (int i = 0; i < 8; i++)
#pragma unroll
                for (int j = 0; j < 8; j++)
                    acc[i][j] += ar[i] * br[j];
        }
        __syncthreads();
    }

    float* Cp = C + (blockIdx.y * 128 + ty * 8) * N + blockIdx.x * 128 + tx * 8;
#pragma unroll
    for (int i = 0; i < 8; i++) {
        *(float4*)&Cp[i * N]     = make_float4(acc[i][0], acc[i][1], acc[i][2], acc[i][3]);
        *(float4*)&Cp[i * N + 4] = make_float4(acc[i][4], acc[i][5], acc[i][6], acc[i][7]);
    }
}

// ---------------------------------------------------------------------------
// Per-head RMSNorm + RoPE, in place on g_qkv. One block = one (token, head).
// heads 0..31 = q (q_norm_w), 32..35 = k (k_norm_w); both start at col h*128.
// ---------------------------------------------------------------------------
__global__ __launch_bounds__(128) void normrope_kernel(float* __restrict__ qkv,
                                                       const float* __restrict__ qw,
                                                       const float* __restrict__ kw,
                                                       const float* __restrict__ cosT,
                                                       const float* __restrict__ sinT) {
    const int row = blockIdx.x;       // 0..2047 (b*S + s)
    const int h   = blockIdx.y;       // 0..35
    const int d   = threadIdx.x;      // 0..127
    const int s   = row & (SS - 1);
    const float* w = (h < NH) ? qw : kw;
    float* p = &qkv[row * QKV_N + h * DH];

    float x  = p[d];
    float sq = x * x;
#pragma unroll
    for (int o = 16; o; o >>= 1) sq += __shfl_xor_sync(0xffffffffu, sq, o);

    __shared__ float wsum[4];
    __shared__ float xs[DH];
    if ((d & 31) == 0) wsum[d >> 5] = sq;
    __syncthreads();
    float tot = wsum[0] + wsum[1] + wsum[2] + wsum[3];
    float r = rsqrtf(tot * (1.f / DH) + EPS);
    float xn = w[d] * x * r;
    xs[d] = xn;
    __syncthreads();
    float rot = (d < 64) ? -xs[d + 64] : xs[d - 64];
    p[d] = xn * cosT[s * DH + d] + rot * sinT[s * DH + d];
}

// ---------------------------------------------------------------------------
// Flash attention (fp32, causal, GQA). Block = (q-tile of 64, head, batch).
// Q/K stored d-major in smem (stride 72, 16B aligned), V row-major, scores
// staged in smem, online softmax with 4 threads per row.
// ---------------------------------------------------------------------------
#define QT_STRIDE 72
#define SMF_QT   (128 * QT_STRIDE)            // 9216
#define SMF_KT   (128 * QT_STRIDE)            // 9216
#define SMF_VS   (64 * 128)                   // 8192
#define SMF_SS   (64 * QT_STRIDE)             // 4608
#define ATTN_SMEM_FLOATS (SMF_QT + SMF_KT + SMF_VS + SMF_SS + 3 * 64)
#define ATTN_SMEM_BYTES  (ATTN_SMEM_FLOATS * 4)   // 125,952 B

__global__ __launch_bounds__(256) void attn_kernel(const float* __restrict__ qkv,
                                                   float* __restrict__ ctx) {
    extern __shared__ float sm[];
    float* Qt = sm;                 // [d=128][q=64], stride 72
    float* Kt = Qt + SMF_QT;        // [d=128][k=64], stride 72
    float* Vs = Kt + SMF_KT;        // [k=64][d=128]
    float* Ss = Vs + SMF_VS;        // [q=64][k=64], stride 72
    float* rm = Ss + SMF_SS;        // row max
    float* rl = rm + 64;            // row sum
    float* ra = rl + 64;            // row alpha

    const int qt = blockIdx.x, h = blockIdx.y, b = blockIdx.z;
    const int kh = h >> 3;          // G = 8
    const int tid = threadIdx.x;
    const int tx = tid & 15, ty = tid >> 4;
    const int rowbase = b * SS;
    const int qbase = qt * 64;
    const int qcol = h * DH;
    const int kcol = NH * DH + kh * DH;
    const int vcol = (NH + NKV) * DH + kh * DH;

    // Load Q tile transposed (lane-over-rows: conflict-free STS, gmem hits L1)
    for (int i = tid; i < 64 * 32; i += 256) {
        int r = i & 63, d4 = (i >> 6) << 2;
        float4 v = *(const float4*)&qkv[(rowbase + qbase + r) * QKV_N + qcol + d4];
        Qt[(d4 + 0) * QT_STRIDE + r] = v.x;
        Qt[(d4 + 1) * QT_STRIDE + r] = v.y;
        Qt[(d4 + 2) * QT_STRIDE + r] = v.z;
        Qt[(d4 + 3) * QT_STRIDE + r] = v.w;
    }
    if (tid < 64) { rm[tid] = -1e30f; rl[tid] = 0.f; }

    float acc[4][8];
#pragma unroll
    for (int i = 0; i < 4; i++)
#pragma unroll
        for (int j = 0; j < 8; j++) acc[i][j] = 0.f;
    __syncthreads();

    for (int kt = 0; kt <= qt; ++kt) {
        const int kbase = kt * 64;
        // K transposed
        for (int i = tid; i < 64 * 32; i += 256) {
            int r = i & 63, d4 = (i >> 6) << 2;
            float4 v = *(const float4*)&qkv[(rowbase + kbase + r) * QKV_N + kcol + d4];
            Kt[(d4 + 0) * QT_STRIDE + r] = v.x;
            Kt[(d4 + 1) * QT_STRIDE + r] = v.y;
            Kt[(d4 + 2) * QT_STRIDE + r] = v.z;
            Kt[(d4 + 3) * QT_STRIDE + r] = v.w;
        }
        // V row-major (coalesced load, conflict-free STS.128)
        for (int i = tid; i < 64 * 32; i += 256) {
            int r = i >> 5, d4 = (i & 31) << 2;
            *(float4*)&Vs[r * 128 + d4] =
                *(const float4*)&qkv[(rowbase + kbase + r) * QKV_N + vcol + d4];
        }
        __syncthreads();

        // Phase 1: S = Q K^T (4x4 microtile on 16x16 thread grid)
        float s[4][4];
#pragma unroll
        for (int i = 0; i < 4; i++)
#pragma unroll
            for (int j = 0; j < 4; j++) s[i][j] = 0.f;

        for (int d = 0; d < 128; ++d) {
            float4 q4 = *(float4*)&Qt[d * QT_STRIDE + ty * 4];
            float4 k4 = *(float4*)&Kt[d * QT_STRIDE + tx * 4];
            float qa[4] = {q4.x, q4.y, q4.z, q4.w};
            float ka[4] = {k4.x, k4.y, k4.z, k4.w};
#pragma unroll
            for (int i = 0; i < 4; i++)
#pragma unroll
                for (int j = 0; j < 4; j++) s[i][j] += qa[i] * ka[j];
        }
        const bool diag = (kt == qt);
#pragma unroll
        for (int i = 0; i < 4; i++) {
            int qrow = qbase + ty * 4 + i;
            float v0 = s[i][0] * ATT_SCALE, v1 = s[i][1] * ATT_SCALE;
            float v2 = s[i][2] * ATT_SCALE, v3 = s[i][3] * ATT_SCALE;
            if (diag) {
                int kc = kbase + tx * 4;
                if (kc + 0 > qrow) v0 = -1e30f;
                if (kc + 1 > qrow) v1 = -1e30f;
                if (kc + 2 > qrow) v2 = -1e30f;
                if (kc + 3 > qrow) v3 = -1e30f;
            }
            *(float4*)&Ss[(ty * 4 + i) * QT_STRIDE + tx * 4] = make_float4(v0, v1, v2, v3);
        }
        __syncthreads();

        // Phase 2: online softmax, 4 threads per row
        {
            const int row = tid >> 2, sub = tid & 3;
            float* srow = &Ss[row * QT_STRIDE + sub * 16];
            float mx = -1e30f;
#pragma unroll
            for (int c = 0; c < 16; c++) mx = fmaxf(mx, srow[c]);
            mx = fmaxf(mx, __shfl_xor_sync(0xffffffffu, mx, 1));
            mx = fmaxf(mx, __shfl_xor_sync(0xffffffffu, mx, 2));
            float mold = rm[row];
            float mnew = fmaxf(mold, mx);
            float ls = 0.f;
#pragma unroll
            for (int c = 0; c < 16; c++) {
                float p = __expf(srow[c] - mnew);
                srow[c] = p;
                ls += p;
            }
            ls += __shfl_xor_sync(0xffffffffu, ls, 1);
            ls += __shfl_xor_sync(0xffffffffu, ls, 2);
            if (sub == 0) {
                float alpha = __expf(mold - mnew);
                rm[row] = mnew;
                rl[row] = rl[row] * alpha + ls;
                ra[row] = alpha;
            }
        }
        __syncthreads();

        // Phase 3: O = O*alpha + P @ V (4 rows x 8 cols per thread)
        {
            float a0 = ra[ty * 4 + 0], a1 = ra[ty * 4 + 1];
            float a2 = ra[ty * 4 + 2], a3 = ra[ty * 4 + 3];
#pragma unroll
            for (int j = 0; j < 8; j++) {
                acc[0][j] *= a0; acc[1][j] *= a1;
                acc[2][j] *= a2; acc[3][j] *= a3;
            }
#pragma unroll 2
            for (int k = 0; k < 64; ++k) {
                float4 v0 = *(float4*)&Vs[k * 128 + tx * 8];
                float4 v1 = *(float4*)&Vs[k * 128 + tx * 8 + 4];
                float vr[8] = {v0.x, v0.y, v0.z, v0.w, v1.x, v1.y, v1.z, v1.w};
                float p0 = Ss[(ty * 4 + 0) * QT_STRIDE + k];
                float p1 = Ss[(ty * 4 + 1) * QT_STRIDE + k];
                float p2 = Ss[(ty * 4 + 2) * QT_STRIDE + k];
                float p3 = Ss[(ty * 4 + 3) * QT_STRIDE + k];
#pragma unroll
                for (int j = 0; j < 8; j++) {
                    acc[0][j] += p0 * vr[j];
                    acc[1][j] += p1 * vr[j];
                    acc[2][j] += p2 * vr[j];
                    acc[3][j] += p3 * vr[j];
                }
            }
        }
        __syncthreads();
    }

    // Epilogue: normalize by row sum, write ctx[token][h*128 + d]
#pragma unroll
    for (int i = 0; i < 4; i++) {
        float inv = 1.f / rl[ty * 4 + i];
        int row = rowbase + qbase + ty * 4 + i;
        float* op = &ctx[row * CTX_N + h * DH + tx * 8];
        *(float4*)(op)     = make_float4(acc[i][0] * inv, acc[i][1] * inv,
                                         acc[i][2] * inv, acc[i][3] * inv);
        *(float4*)(op + 4) = make_float4(acc[i][4] * inv, acc[i][5] * inv,
                                         acc[i][6] * inv, acc[i][7] * inv);
    }
}

// ---------------------------------------------------------------------------
extern "C" void kernel_launch(void* const* d_in, const int* in_sizes, int n_in,
                              void* d_out, int out_size) {
    const float* hidden = (const float*)d_in[0];   // [B,S,HID]
    const float* cosT   = (const float*)d_in[1];   // [1,S,1,D]
    const float* sinT   = (const float*)d_in[2];
    const float* w_qkv  = (const float*)d_in[3];   // [HID, 5120]
    const float* qw     = (const float*)d_in[4];   // [128]
    const float* kw     = (const float*)d_in[5];   // [128]
    const float* w_o    = (const float*)d_in[6];   // [4096, HID]
    float* out = (float*)d_out;                    // [B,S,HID]

    float *qkv, *ctx;
    cudaGetSymbolAddress((void**)&qkv, g_qkv);
    cudaGetSymbolAddress((void**)&ctx, g_ctx);

    // 1) QKV projection: [2048,2048] @ [2048,5120]
    sgemm128<<<dim3(QKV_N / 128, NTOK / 128), 256>>>(hidden, w_qkv, qkv,
                                                     NTOK, QKV_N, HID);
    // 2) RMSNorm + RoPE on q and k heads (in place)
    normrope_kernel<<<dim3(NTOK, NH + NKV), 128>>>(qkv, qw, kw, cosT, sinT);

    // 3) Causal GQA flash attention
    cudaFuncSetAttribute(attn_kernel, cudaFuncAttributeMaxDynamicSharedMemorySize,
                         ATTN_SMEM_BYTES);
    attn_kernel<<<dim3(SS / 64, NH, BB), 256, ATTN_SMEM_BYTES>>>(qkv, ctx);

    // 4) Output projection: [2048,4096] @ [4096,2048]
    sgemm128<<<dim3(HID / 128, NTOK / 128), 256>>>(ctx, w_o, out,
                                                   NTOK, HID, CTX_N);
}

// round 7
// speedup vs baseline: 2.8483x; 2.8483x over previous
#include <cuda_runtime.h>
#include <cstdint>
#include <cstddef>

// Problem constants
#define BB   2
#define SS   1024
#define HID  2048
#define NH   32
#define NKV  4
#define DH   128
#define QKV_N 5120          // (32 + 2*4) * 128
#define CTX_N 4096          // 32 * 128
#define NTOK  2048          // B*S
#define ATT_SCALE 0.08838834764831845f   // 1/sqrt(128)
#define EPS  1e-6f

// Scratch (no cudaMalloc allowed)
__device__ float g_qkv[NTOK * QKV_N];      // 40 MiB
__device__ float g_ctx[NTOK * CTX_N];      // 32 MiB
__device__ float g_wqkvT[QKV_N * HID];     // 40 MiB  (w_qkv^T, [N,K])
__device__ float g_woT[HID * CTX_N];       // 32 MiB  (w_o^T,   [N,K])

__device__ __forceinline__ uint32_t smem_u32(const void* p) {
    uint32_t a;
    asm("{ .reg .u64 t; cvta.to.shared.u64 t, %1; cvt.u32.u64 %0, t; }"
        : "=r"(a) : "l"(p));
    return a;
}

__device__ __forceinline__ float to_tf32(float x) {
    float r;
    asm("cvt.rna.tf32.f32 %0, %1;" : "=f"(r) : "f"(x));
    return r;
}

// ---------------------------------------------------------------------------
// 32x32 tiled transpose: dst[C,R] = src[R,C]^T   (R,C multiples of 32)
// ---------------------------------------------------------------------------
__global__ __launch_bounds__(256) void transpose32(const float* __restrict__ src,
                                                   float* __restrict__ dst,
                                                   int R, int C) {
    __shared__ float t[32][33];
    const int c0 = blockIdx.x * 32, r0 = blockIdx.y * 32;
    const int x = threadIdx.x & 31, y4 = (threadIdx.x >> 5) * 4;
#pragma unroll
    for (int i = 0; i < 4; i++)
        t[y4 + i][x] = src[(size_t)(r0 + y4 + i) * C + c0 + x];
    __syncthreads();
#pragma unroll
    for (int i = 0; i < 4; i++)
        dst[(size_t)(c0 + y4 + i) * R + r0 + x] = t[x][y4 + i];
}

// ---------------------------------------------------------------------------
// TF32 tensor-core GEMM via mma.sync (base-target safe, no tcgen05):
//   C[M,N] = A[M,K] @ Bt[N,K]^T, fp32 in/out, RNA->tf32 on the smem path.
// CTA 128x128, BK=32, 8 warps (2m x 4n), warp tile 64x32,
// m16n8k8 fragments, smem pre-scattered into fragment layout:
//   A: per (m16,k8) block of 132 words: lane*4 + reg  (LDS.128 loads)
//   B: per (n8, k8) block of  66 words: lane*2 + reg  (LDS.64 loads)
// ---------------------------------------------------------------------------
#define ABLK 132                 // words per (m16,k8) block (128 + 4 pad)
#define BBLK 66                  // words per (n8, k8) block (64 + 2 pad)
#define AW   (32 * ABLK)         // 8 m16-tiles * 4 k8-slabs
#define BW   (64 * BBLK)         // 16 n8-tiles * 4 k8-slabs
#define BUFW (AW + BW)           // 8448 words per buffer
#define GM_SMEM_BYTES (2 * BUFW * 4)   // 67584 B

__global__ __launch_bounds__(256) void gemm_mma(const float* __restrict__ A,
                                                const float* __restrict__ Bt,
                                                float* __restrict__ C,
                                                int M, int N, int K) {
    extern __shared__ float sm[];
    const int tid = threadIdx.x, lane = tid & 31, wid = tid >> 5;
    const int wm = wid & 1, wn = wid >> 1;       // warp grid 2(m) x 4(n)
    const int m0 = blockIdx.x << 7, n0 = blockIdx.y << 7;

    // gmem staging: thread handles rows r0 + i*32, float4 at k4
    const int k4 = tid & 7;                      // k = 4*k4 within 32-chunk
    const int r0 = tid >> 3;                     // 0..31
    const int k8 = k4 >> 1, khalf = k4 & 1;

    const float* Ag = A + (size_t)(m0 + r0) * K + k4 * 4;
    const float* Bg = Bt + (size_t)(n0 + r0) * K + k4 * 4;

    float4 ra[4], rb[4];
    float d[4][4][4];
#pragma unroll
    for (int mt = 0; mt < 4; mt++)
#pragma unroll
        for (int nt = 0; nt < 4; nt++)
#pragma unroll
            for (int j = 0; j < 4; j++) d[mt][nt][j] = 0.f;

    const int KT = K >> 5;
    const uint32_t sbase = smem_u32(sm);

    // prologue: load chunk 0
#pragma unroll
    for (int i = 0; i < 4; i++) {
        ra[i] = *(const float4*)(Ag + (size_t)(i * 32) * K);
        rb[i] = *(const float4*)(Bg + (size_t)(i * 32) * K);
    }
    // scatter chunk 0 into buffer 0
    {
        float* sA = sm;
        float* sB = sm + AW;
#pragma unroll
        for (int i = 0; i < 4; i++) {
            const int m = i * 32 + r0;
            float* p = sA + ((m >> 4) * 4 + k8) * ABLK
                          + (m & 7) * 16 + ((m >> 3) & 1) + 2 * khalf;
            p[0]  = to_tf32(ra[i].x);
            p[4]  = to_tf32(ra[i].y);
            p[8]  = to_tf32(ra[i].z);
            p[12] = to_tf32(ra[i].w);
            float* q = sB + ((m >> 3) * 4 + k8) * BBLK + (m & 7) * 8 + khalf;
            q[0] = to_tf32(rb[i].x);
            q[2] = to_tf32(rb[i].y);
            q[4] = to_tf32(rb[i].z);
            q[6] = to_tf32(rb[i].w);
        }
    }
    __syncthreads();

    for (int kt = 0; kt < KT; ++kt) {
        const int cur = kt & 1;
        const bool more = (kt + 1 < KT);
        if (more) {
            const size_t koff = (size_t)(kt + 1) * 32;
#pragma unroll
            for (int i = 0; i < 4; i++) {
                ra[i] = *(const float4*)(Ag + (size_t)(i * 32) * K + koff);
                rb[i] = *(const float4*)(Bg + (size_t)(i * 32) * K + koff);
            }
        }

        // MMA over current buffer
        {
            const uint32_t aB = sbase + (uint32_t)(cur * BUFW) * 4;
            const uint32_t bB = aB + AW * 4;
#pragma unroll
            for (int kk = 0; kk < 4; ++kk) {
                uint32_t af[4][4], bf[4][2];
#pragma unroll
                for (int mt = 0; mt < 4; mt++) {
                    uint32_t addr = aB + (uint32_t)((((wm * 4 + mt) * 4 + kk) * ABLK
                                                    + lane * 4) * 4);
                    asm volatile("ld.shared.v4.b32 {%0,%1,%2,%3}, [%4];"
                                 : "=r"(af[mt][0]), "=r"(af[mt][1]),
                                   "=r"(af[mt][2]), "=r"(af[mt][3])
                                 : "r"(addr));
                }
#pragma unroll
                for (int nt = 0; nt < 4; nt++) {
                    uint32_t addr = bB + (uint32_t)((((wn * 4 + nt) * 4 + kk) * BBLK
                                                    + lane * 2) * 4);
                    asm volatile("ld.shared.v2.b32 {%0,%1}, [%2];"
                                 : "=r"(bf[nt][0]), "=r"(bf[nt][1])
                                 : "r"(addr));
                }
#pragma unroll
                for (int mt = 0; mt < 4; mt++)
#pragma unroll
                    for (int nt = 0; nt < 4; nt++) {
                        asm volatile(
                            "mma.sync.aligned.m16n8k8.row.col.f32.tf32.tf32.f32 "
                            "{%0,%1,%2,%3}, {%4,%5,%6,%7}, {%8,%9}, {%0,%1,%2,%3};"
                            : "+f"(d[mt][nt][0]), "+f"(d[mt][nt][1]),
                              "+f"(d[mt][nt][2]), "+f"(d[mt][nt][3])
                            : "r"(af[mt][0]), "r"(af[mt][1]),
                              "r"(af[mt][2]), "r"(af[mt][3]),
                              "r"(bf[nt][0]), "r"(bf[nt][1]));
                    }
            }
        }

        // scatter next chunk into the other buffer
        if (more) {
            float* sA = sm + (cur ^ 1) * BUFW;
            float* sB = sA + AW;
#pragma unroll
            for (int i = 0; i < 4; i++) {
                const int m = i * 32 + r0;
                float* p = sA + ((m >> 4) * 4 + k8) * ABLK
                              + (m & 7) * 16 + ((m >> 3) & 1) + 2 * khalf;
                p[0]  = to_tf32(ra[i].x);
                p[4]  = to_tf32(ra[i].y);
                p[8]  = to_tf32(ra[i].z);
                p[12] = to_tf32(ra[i].w);
                float* q = sB + ((m >> 3) * 4 + k8) * BBLK + (m & 7) * 8 + khalf;
                q[0] = to_tf32(rb[i].x);
                q[2] = to_tf32(rb[i].y);
                q[4] = to_tf32(rb[i].z);
                q[6] = to_tf32(rb[i].w);
            }
        }
        __syncthreads();
    }

    // Epilogue: write C (c0,c1 -> row g, c2,c3 -> row g+8; cols 2t, 2t+1)
    const int g = lane >> 2, t = lane & 3;
#pragma unroll
    for (int mt = 0; mt < 4; mt++) {
        const int row = m0 + wm * 64 + mt * 16 + g;
#pragma unroll
        for (int nt = 0; nt < 4; nt++) {
            const int col = n0 + wn * 32 + nt * 8 + t * 2;
            *(float2*)&C[(size_t)row * N + col] =
                make_float2(d[mt][nt][0], d[mt][nt][1]);
            *(float2*)&C[(size_t)(row + 8) * N + col] =
                make_float2(d[mt][nt][2], d[mt][nt][3]);
        }
    }
}

// ---------------------------------------------------------------------------
// Per-head RMSNorm + RoPE, in place on g_qkv. One block = one (token, head).
// ---------------------------------------------------------------------------
__global__ __launch_bounds__(128) void normrope_kernel(float* __restrict__ qkv,
                                                       const float* __restrict__ qw,
                                                       const float* __restrict__ kw,
                                                       const float* __restrict__ cosT,
                                                       const float* __restrict__ sinT) {
    const int row = blockIdx.x;       // 0..2047 (b*S + s)
    const int h   = blockIdx.y;       // 0..35
    const int d   = threadIdx.x;      // 0..127
    const int s   = row & (SS - 1);
    const float* w = (h < NH) ? qw : kw;
    float* p = &qkv[row * QKV_N + h * DH];

    float x  = p[d];
    float sq = x * x;
#pragma unroll
    for (int o = 16; o; o >>= 1) sq += __shfl_xor_sync(0xffffffffu, sq, o);

    __shared__ float wsum[4];
    __shared__ float xs[DH];
    if ((d & 31) == 0) wsum[d >> 5] = sq;
    __syncthreads();
    float tot = wsum[0] + wsum[1] + wsum[2] + wsum[3];
    float r = rsqrtf(tot * (1.f / DH) + EPS);
    float xn = w[d] * x * r;
    xs[d] = xn;
    __syncthreads();
    float rot = (d < 64) ? -xs[d + 64] : xs[d - 64];
    p[d] = xn * cosT[s * DH + d] + rot * sinT[s * DH + d];
}

// ---------------------------------------------------------------------------
// Flash attention (fp32, causal, GQA) — proven R4 version, unchanged.
// ---------------------------------------------------------------------------
#define QT_STRIDE 72
#define SMF_QT   (128 * QT_STRIDE)
#define SMF_KT   (128 * QT_STRIDE)
#define SMF_VS   (64 * 128)
#define SMF_SS   (64 * QT_STRIDE)
#define ATTN_SMEM_FLOATS (SMF_QT + SMF_KT + SMF_VS + SMF_SS + 3 * 64)
#define ATTN_SMEM_BYTES  (ATTN_SMEM_FLOATS * 4)

__global__ __launch_bounds__(256) void attn_kernel(const float* __restrict__ qkv,
                                                   float* __restrict__ ctx) {
    extern __shared__ float sm[];
    float* Qt = sm;
    float* Kt = Qt + SMF_QT;
    float* Vs = Kt + SMF_KT;
    float* Ss = Vs + SMF_VS;
    float* rm = Ss + SMF_SS;
    float* rl = rm + 64;
    float* ra = rl + 64;

    const int qt = blockIdx.x, h = blockIdx.y, b = blockIdx.z;
    const int kh = h >> 3;
    const int tid = threadIdx.x;
    const int tx = tid & 15, ty = tid >> 4;
    const int rowbase = b * SS;
    const int qbase = qt * 64;
    const int qcol = h * DH;
    const int kcol = NH * DH + kh * DH;
    const int vcol = (NH + NKV) * DH + kh * DH;

    for (int i = tid; i < 64 * 32; i += 256) {
        int r = i & 63, d4 = (i >> 6) << 2;
        float4 v = *(const float4*)&qkv[(rowbase + qbase + r) * QKV_N + qcol + d4];
        Qt[(d4 + 0) * QT_STRIDE + r] = v.x;
        Qt[(d4 + 1) * QT_STRIDE + r] = v.y;
        Qt[(d4 + 2) * QT_STRIDE + r] = v.z;
        Qt[(d4 + 3) * QT_STRIDE + r] = v.w;
    }
    if (tid < 64) { rm[tid] = -1e30f; rl[tid] = 0.f; }

    float acc[4][8];
#pragma unroll
    for (int i = 0; i < 4; i++)
#pragma unroll
        for (int j = 0; j < 8; j++) acc[i][j] = 0.f;
    __syncthreads();

    for (int kt = 0; kt <= qt; ++kt) {
        const int kbase = kt * 64;
        for (int i = tid; i < 64 * 32; i += 256) {
            int r = i & 63, d4 = (i >> 6) << 2;
            float4 v = *(const float4*)&qkv[(rowbase + kbase + r) * QKV_N + kcol + d4];
            Kt[(d4 + 0) * QT_STRIDE + r] = v.x;
            Kt[(d4 + 1) * QT_STRIDE + r] = v.y;
            Kt[(d4 + 2) * QT_STRIDE + r] = v.z;
            Kt[(d4 + 3) * QT_STRIDE + r] = v.w;
        }
        for (int i = tid; i < 64 * 32; i += 256) {
            int r = i >> 5, d4 = (i & 31) << 2;
            *(float4*)&Vs[r * 128 + d4] =
                *(const float4*)&qkv[(rowbase + kbase + r) * QKV_N + vcol + d4];
        }
        __syncthreads();

        float s[4][4];
#pragma unroll
        for (int i = 0; i < 4; i++)
#pragma unroll
            for (int j = 0; j < 4; j++) s[i][j] = 0.f;

        for (int d = 0; d < 128; ++d) {
            float4 q4 = *(float4*)&Qt[d * QT_STRIDE + ty * 4];
            float4 k4 = *(float4*)&Kt[d * QT_STRIDE + tx * 4];
            float qa[4] = {q4.x, q4.y, q4.z, q4.w};
            float ka[4] = {k4.x, k4.y, k4.z, k4.w};
#pragma unroll
            for (int i = 0; i < 4; i++)
#pragma unroll
                for (int j = 0; j < 4; j++) s[i][j] += qa[i] * ka[j];
        }
        const bool diag = (kt == qt);
#pragma unroll
        for (int i = 0; i < 4; i++) {
            int qrow = qbase + ty * 4 + i;
            float v0 = s[i][0] * ATT_SCALE, v1 = s[i][1] * ATT_SCALE;
            float v2 = s[i][2] * ATT_SCALE, v3 = s[i][3] * ATT_SCALE;
            if (diag) {
                int kc = kbase + tx * 4;
                if (kc + 0 > qrow) v0 = -1e30f;
                if (kc + 1 > qrow) v1 = -1e30f;
                if (kc + 2 > qrow) v2 = -1e30f;
                if (kc + 3 > qrow) v3 = -1e30f;
            }
            *(float4*)&Ss[(ty * 4 + i) * QT_STRIDE + tx * 4] = make_float4(v0, v1, v2, v3);
        }
        __syncthreads();

        {
            const int row = tid >> 2, sub = tid & 3;
            float* srow = &Ss[row * QT_STRIDE + sub * 16];
            float mx = -1e30f;
#pragma unroll
            for (int c = 0; c < 16; c++) mx = fmaxf(mx, srow[c]);
            mx = fmaxf(mx, __shfl_xor_sync(0xffffffffu, mx, 1));
            mx = fmaxf(mx, __shfl_xor_sync(0xffffffffu, mx, 2));
            float mold = rm[row];
            float mnew = fmaxf(mold, mx);
            float ls = 0.f;
#pragma unroll
            for (int c = 0; c < 16; c++) {
                float p = __expf(srow[c] - mnew);
                srow[c] = p;
                ls += p;
            }
            ls += __shfl_xor_sync(0xffffffffu, ls, 1);
            ls += __shfl_xor_sync(0xffffffffu, ls, 2);
            if (sub == 0) {
                float alpha = __expf(mold - mnew);
                rm[row] = mnew;
                rl[row] = rl[row] * alpha + ls;
                ra[row] = alpha;
            }
        }
        __syncthreads();

        {
            float a0 = ra[ty * 4 + 0], a1 = ra[ty * 4 + 1];
            float a2 = ra[ty * 4 + 2], a3 = ra[ty * 4 + 3];
#pragma unroll
            for (int j = 0; j < 8; j++) {
                acc[0][j] *= a0; acc[1][j] *= a1;
                acc[2][j] *= a2; acc[3][j] *= a3;
            }
#pragma unroll 2
            for (int k = 0; k < 64; ++k) {
                float4 v0 = *(float4*)&Vs[k * 128 + tx * 8];
                float4 v1 = *(float4*)&Vs[k * 128 + tx * 8 + 4];
                float vr[8] = {v0.x, v0.y, v0.z, v0.w, v1.x, v1.y, v1.z, v1.w};
                float p0 = Ss[(ty * 4 + 0) * QT_STRIDE + k];
                float p1 = Ss[(ty * 4 + 1) * QT_STRIDE + k];
                float p2 = Ss[(ty * 4 + 2) * QT_STRIDE + k];
                float p3 = Ss[(ty * 4 + 3) * QT_STRIDE + k];
#pragma unroll
                for (int j = 0; j < 8; j++) {
                    acc[0][j] += p0 * vr[j];
                    acc[1][j] += p1 * vr[j];
                    acc[2][j] += p2 * vr[j];
                    acc[3][j] += p3 * vr[j];
                }
            }
        }
        __syncthreads();
    }

#pragma unroll
    for (int i = 0; i < 4; i++) {
        float inv = 1.f / rl[ty * 4 + i];
        int row = rowbase + qbase + ty * 4 + i;
        float* op = &ctx[row * CTX_N + h * DH + tx * 8];
        *(float4*)(op)     = make_float4(acc[i][0] * inv, acc[i][1] * inv,
                                         acc[i][2] * inv, acc[i][3] * inv);
        *(float4*)(op + 4) = make_float4(acc[i][4] * inv, acc[i][5] * inv,
                                         acc[i][6] * inv, acc[i][7] * inv);
    }
}

// ---------------------------------------------------------------------------
extern "C" void kernel_launch(void* const* d_in, const int* in_sizes, int n_in,
                              void* d_out, int out_size) {
    const float* hidden = (const float*)d_in[0];   // [B,S,HID]
    const float* cosT   = (const float*)d_in[1];   // [1,S,1,D]
    const float* sinT   = (const float*)d_in[2];
    const float* w_qkv  = (const float*)d_in[3];   // [HID, 5120]
    const float* qw     = (const float*)d_in[4];   // [128]
    const float* kw     = (const float*)d_in[5];   // [128]
    const float* w_o    = (const float*)d_in[6];   // [4096, HID]
    float* out = (float*)d_out;                    // [B,S,HID]

    float *qkv, *ctx, *wqkvT, *woT;
    cudaGetSymbolAddress((void**)&qkv,   g_qkv);
    cudaGetSymbolAddress((void**)&ctx,   g_ctx);
    cudaGetSymbolAddress((void**)&wqkvT, g_wqkvT);
    cudaGetSymbolAddress((void**)&woT,   g_woT);

    cudaFuncSetAttribute(gemm_mma, cudaFuncAttributeMaxDynamicSharedMemorySize,
                         GM_SMEM_BYTES);
    cudaFuncSetAttribute(attn_kernel, cudaFuncAttributeMaxDynamicSharedMemorySize,
                         ATTN_SMEM_BYTES);

    // 0) Weight transposes to [N,K] for K-major B operand
    transpose32<<<dim3(QKV_N / 32, HID / 32), 256>>>(w_qkv, wqkvT, HID, QKV_N);
    transpose32<<<dim3(HID / 32, CTX_N / 32), 256>>>(w_o, woT, CTX_N, HID);

    // 1) QKV projection (mma.sync tf32): [2048,2048] @ [2048,5120]
    gemm_mma<<<dim3(NTOK / 128, QKV_N / 128), 256, GM_SMEM_BYTES>>>(
        hidden, wqkvT, qkv, NTOK, QKV_N, HID);

    // 2) RMSNorm + RoPE on q and k heads (in place)
    normrope_kernel<<<dim3(NTOK, NH + NKV), 128>>>(qkv, qw, kw, cosT, sinT);

    // 3) Causal GQA flash attention (fp32)
    attn_kernel<<<dim3(SS / 64, NH, BB), 256, ATTN_SMEM_BYTES>>>(qkv, ctx);

    // 4) Output projection (mma.sync tf32): [2048,4096] @ [4096,2048]
    gemm_mma<<<dim3(NTOK / 128, HID / 128), 256, GM_SMEM_BYTES>>>(
        ctx, woT, out, NTOK, HID, CTX_N);
}

// round 11
// speedup vs baseline: 4.5913x; 1.6120x over previous
#include <cuda_runtime.h>
#include <cstdint>
#include <cstddef>

// Problem constants
#define BB   2
#define SS   1024
#define HID  2048
#define NH   32
#define NKV  4
#define DH   128
#define QKV_N 5120          // (32 + 2*4) * 128
#define CTX_N 4096          // 32 * 128
#define NTOK  2048          // B*S
#define ATT_SCALE 0.08838834764831845f   // 1/sqrt(128)
#define EPS  1e-6f

// Scratch (no cudaMalloc allowed)
__device__ float g_qkv[NTOK * QKV_N];      // 40 MiB
__device__ float g_ctx[NTOK * CTX_N];      // 32 MiB
__device__ float g_wqkvT[QKV_N * HID];     // 40 MiB  (w_qkv^T, [N,K])
__device__ float g_woT[HID * CTX_N];       // 32 MiB  (w_o^T,   [N,K])

__device__ __forceinline__ uint32_t smem_u32(const void* p) {
    uint32_t a;
    asm("{ .reg .u64 t; cvta.to.shared.u64 t, %1; cvt.u32.u64 %0, t; }"
        : "=r"(a) : "l"(p));
    return a;
}

__device__ __forceinline__ float to_tf32(float x) {
    float r;
    asm("cvt.rna.tf32.f32 %0, %1;" : "=f"(r) : "f"(x));
    return r;
}

#define MMA_TF32(d0, d1, d2, d3, a0, a1, a2, a3, b0, b1)                        \
    asm volatile(                                                               \
        "mma.sync.aligned.m16n8k8.row.col.f32.tf32.tf32.f32 "                   \
        "{%0,%1,%2,%3}, {%4,%5,%6,%7}, {%8,%9}, {%0,%1,%2,%3};"                 \
        : "+f"(d0), "+f"(d1), "+f"(d2), "+f"(d3)                                \
        : "r"(a0), "r"(a1), "r"(a2), "r"(a3), "r"(b0), "r"(b1))

// ---------------------------------------------------------------------------
// 32x32 tiled transpose: dst[C,R] = src[R,C]^T   (R,C multiples of 32)
// ---------------------------------------------------------------------------
__global__ __launch_bounds__(256) void transpose32(const float* __restrict__ src,
                                                   float* __restrict__ dst,
                                                   int R, int C) {
    __shared__ float t[32][33];
    const int c0 = blockIdx.x * 32, r0 = blockIdx.y * 32;
    const int x = threadIdx.x & 31, y4 = (threadIdx.x >> 5) * 4;
#pragma unroll
    for (int i = 0; i < 4; i++)
        t[y4 + i][x] = src[(size_t)(r0 + y4 + i) * C + c0 + x];
    __syncthreads();
#pragma unroll
    for (int i = 0; i < 4; i++)
        dst[(size_t)(c0 + y4 + i) * R + r0 + x] = t[x][y4 + i];
}

// ---------------------------------------------------------------------------
// TF32 tensor-core GEMM via mma.sync (proven R7 version):
//   C[M,N] = A[M,K] @ Bt[N,K]^T, fp32 in/out, RNA->tf32 on the smem path.
// ---------------------------------------------------------------------------
#define ABLK 132                 // words per (m16,k8) block (128 + 4 pad)
#define BBLK 66                  // words per (n8, k8) block (64 + 2 pad)
#define AW   (32 * ABLK)
#define BW   (64 * BBLK)
#define BUFW (AW + BW)
#define GM_SMEM_BYTES (2 * BUFW * 4)   // 67584 B

__global__ __launch_bounds__(256) void gemm_mma(const float* __restrict__ A,
                                                const float* __restrict__ Bt,
                                                float* __restrict__ C,
                                                int M, int N, int K) {
    extern __shared__ float sm[];
    const int tid = threadIdx.x, lane = tid & 31, wid = tid >> 5;
    const int wm = wid & 1, wn = wid >> 1;       // warp grid 2(m) x 4(n)
    const int m0 = blockIdx.x << 7, n0 = blockIdx.y << 7;

    const int k4 = tid & 7;                      // k = 4*k4 within 32-chunk
    const int r0 = tid >> 3;                     // 0..31
    const int k8 = k4 >> 1, khalf = k4 & 1;

    const float* Ag = A + (size_t)(m0 + r0) * K + k4 * 4;
    const float* Bg = Bt + (size_t)(n0 + r0) * K + k4 * 4;

    float4 ra[4], rb[4];
    float d[4][4][4];
#pragma unroll
    for (int mt = 0; mt < 4; mt++)
#pragma unroll
        for (int nt = 0; nt < 4; nt++)
#pragma unroll
            for (int j = 0; j < 4; j++) d[mt][nt][j] = 0.f;

    const int KT = K >> 5;
    const uint32_t sbase = smem_u32(sm);

#pragma unroll
    for (int i = 0; i < 4; i++) {
        ra[i] = *(const float4*)(Ag + (size_t)(i * 32) * K);
        rb[i] = *(const float4*)(Bg + (size_t)(i * 32) * K);
    }
    {
        float* sA = sm;
        float* sB = sm + AW;
#pragma unroll
        for (int i = 0; i < 4; i++) {
            const int m = i * 32 + r0;
            float* p = sA + ((m >> 4) * 4 + k8) * ABLK
                          + (m & 7) * 16 + ((m >> 3) & 1) + 2 * khalf;
            p[0]  = to_tf32(ra[i].x);
            p[4]  = to_tf32(ra[i].y);
            p[8]  = to_tf32(ra[i].z);
            p[12] = to_tf32(ra[i].w);
            float* q = sB + ((m >> 3) * 4 + k8) * BBLK + (m & 7) * 8 + khalf;
            q[0] = to_tf32(rb[i].x);
            q[2] = to_tf32(rb[i].y);
            q[4] = to_tf32(rb[i].z);
            q[6] = to_tf32(rb[i].w);
        }
    }
    __syncthreads();

    for (int kt = 0; kt < KT; ++kt) {
        const int cur = kt & 1;
        const bool more = (kt + 1 < KT);
        if (more) {
            const size_t koff = (size_t)(kt + 1) * 32;
#pragma unroll
            for (int i = 0; i < 4; i++) {
                ra[i] = *(const float4*)(Ag + (size_t)(i * 32) * K + koff);
                rb[i] = *(const float4*)(Bg + (size_t)(i * 32) * K + koff);
            }
        }

        {
            const uint32_t aB = sbase + (uint32_t)(cur * BUFW) * 4;
            const uint32_t bB = aB + AW * 4;
#pragma unroll
            for (int kk = 0; kk < 4; ++kk) {
                uint32_t af[4][4], bf[4][2];
#pragma unroll
                for (int mt = 0; mt < 4; mt++) {
                    uint32_t addr = aB + (uint32_t)((((wm * 4 + mt) * 4 + kk) * ABLK
                                                    + lane * 4) * 4);
                    asm volatile("ld.shared.v4.b32 {%0,%1,%2,%3}, [%4];"
                                 : "=r"(af[mt][0]), "=r"(af[mt][1]),
                                   "=r"(af[mt][2]), "=r"(af[mt][3])
                                 : "r"(addr));
                }
#pragma unroll
                for (int nt = 0; nt < 4; nt++) {
                    uint32_t addr = bB + (uint32_t)((((wn * 4 + nt) * 4 + kk) * BBLK
                                                    + lane * 2) * 4);
                    asm volatile("ld.shared.v2.b32 {%0,%1}, [%2];"
                                 : "=r"(bf[nt][0]), "=r"(bf[nt][1])
                                 : "r"(addr));
                }
#pragma unroll
                for (int mt = 0; mt < 4; mt++)
#pragma unroll
                    for (int nt = 0; nt < 4; nt++)
                        MMA_TF32(d[mt][nt][0], d[mt][nt][1], d[mt][nt][2], d[mt][nt][3],
                                 af[mt][0], af[mt][1], af[mt][2], af[mt][3],
                                 bf[nt][0], bf[nt][1]);
            }
        }

        if (more) {
            float* sA = sm + (cur ^ 1) * BUFW;
            float* sB = sA + AW;
#pragma unroll
            for (int i = 0; i < 4; i++) {
                const int m = i * 32 + r0;
                float* p = sA + ((m >> 4) * 4 + k8) * ABLK
                              + (m & 7) * 16 + ((m >> 3) & 1) + 2 * khalf;
                p[0]  = to_tf32(ra[i].x);
                p[4]  = to_tf32(ra[i].y);
                p[8]  = to_tf32(ra[i].z);
                p[12] = to_tf32(ra[i].w);
                float* q = sB + ((m >> 3) * 4 + k8) * BBLK + (m & 7) * 8 + khalf;
                q[0] = to_tf32(rb[i].x);
                q[2] = to_tf32(rb[i].y);
                q[4] = to_tf32(rb[i].z);
                q[6] = to_tf32(rb[i].w);
            }
        }
        __syncthreads();
    }

    const int g = lane >> 2, t = lane & 3;
#pragma unroll
    for (int mt = 0; mt < 4; mt++) {
        const int row = m0 + wm * 64 + mt * 16 + g;
#pragma unroll
        for (int nt = 0; nt < 4; nt++) {
            const int col = n0 + wn * 32 + nt * 8 + t * 2;
            *(float2*)&C[(size_t)row * N + col] =
                make_float2(d[mt][nt][0], d[mt][nt][1]);
            *(float2*)&C[(size_t)(row + 8) * N + col] =
                make_float2(d[mt][nt][2], d[mt][nt][3]);
        }
    }
}

// ---------------------------------------------------------------------------
// Per-head RMSNorm + RoPE, in place on g_qkv.
// ---------------------------------------------------------------------------
__global__ __launch_bounds__(128) void normrope_kernel(float* __restrict__ qkv,
                                                       const float* __restrict__ qw,
                                                       const float* __restrict__ kw,
                                                       const float* __restrict__ cosT,
                                                       const float* __restrict__ sinT) {
    const int row = blockIdx.x;
    const int h   = blockIdx.y;
    const int d   = threadIdx.x;
    const int s   = row & (SS - 1);
    const float* w = (h < NH) ? qw : kw;
    float* p = &qkv[row * QKV_N + h * DH];

    float x  = p[d];
    float sq = x * x;
#pragma unroll
    for (int o = 16; o; o >>= 1) sq += __shfl_xor_sync(0xffffffffu, sq, o);

    __shared__ float wsum[4];
    __shared__ float xs[DH];
    if ((d & 31) == 0) wsum[d >> 5] = sq;
    __syncthreads();
    float tot = wsum[0] + wsum[1] + wsum[2] + wsum[3];
    float r = rsqrtf(tot * (1.f / DH) + EPS);
    float xn = w[d] * x * r;
    xs[d] = xn;
    __syncthreads();
    float rot = (d < 64) ? -xs[d + 64] : xs[d - 64];
    p[d] = xn * cosT[s * DH + d] + rot * sinT[s * DH + d];
}

// ---------------------------------------------------------------------------
// Tensor-core flash attention (TF32 mma.sync, causal, GQA).
// CTA = (q-tile of 128, head, batch). 8 warps, warp owns 16 q-rows.
// Smem fragment layouts identical to gemm_mma's (A: 132-word blocks, B: 66).
//   Qa: A-operand of S   (m=q rows,  k=d)      8 mtiles x 16 kslabs
//   Kb: B-operand of S   (n=keys,    k=d)      8 ntiles x 16 kslabs
//   Vb: B-operand of PV  (n=d,       k=keys)  16 ntiles x  8 kslabs
//   Pa: A-operand of PV  (m=q rows,  k=keys)   8 mtiles x  8 kslabs (warp-private)
// ---------------------------------------------------------------------------
#define AT_QA_W (8 * 16 * ABLK)     // 16896
#define AT_KB_W (8 * 16 * BBLK)     //  8448
#define AT_VB_W (16 * 8 * BBLK)     //  8448
#define AT_PA_W (8 * 8 * ABLK)      //  8448
#define AT_SMEM_BYTES ((AT_QA_W + AT_KB_W + AT_VB_W + AT_PA_W) * 4)  // 168960

__global__ __launch_bounds__(256) void attn_tc(const float* __restrict__ qkv,
                                               float* __restrict__ ctx) {
    extern __shared__ float sm[];
    float* Qa = sm;
    float* Kb = Qa + AT_QA_W;
    float* Vb = Kb + AT_KB_W;
    float* Pa = Vb + AT_VB_W;
    const uint32_t qa_u = smem_u32(Qa), kb_u = smem_u32(Kb);
    const uint32_t vb_u = smem_u32(Vb), pa_u = smem_u32(Pa);

    const int qt = (int)gridDim.x - 1 - (int)blockIdx.x;   // heavy tiles first
    const int h = blockIdx.y, b = blockIdx.z;
    const int kh = h >> 3;
    const int tid = threadIdx.x, lane = tid & 31, wid = tid >> 5;
    const int g = lane >> 2, t = lane & 3;
    const int rowbase = b * SS, qbase = qt * 128;
    const int qcol = h * DH;
    const int kcol = NH * DH + kh * DH;
    const int vcol = (NH + NKV) * DH + kh * DH;

    // ---- stage Q tile (128 x 128) into A-fragment layout ----
#pragma unroll
    for (int i = 0; i < 16; i++) {
        int idx = tid + i * 256;              // 4096 float4s
        int row = idx >> 5, k4 = idx & 31;
        float4 v = *(const float4*)&qkv[(size_t)(rowbase + qbase + row) * QKV_N
                                        + qcol + k4 * 4];
        int ks = k4 >> 1, khalf = k4 & 1;
        float* p = Qa + ((row >> 4) * 16 + ks) * ABLK
                      + (row & 7) * 16 + ((row >> 3) & 1) + 2 * khalf;
        p[0]  = to_tf32(v.x);
        p[4]  = to_tf32(v.y);
        p[8]  = to_tf32(v.z);
        p[12] = to_tf32(v.w);
    }

    float o[16][4];
#pragma unroll
    for (int dn = 0; dn < 16; dn++)
#pragma unroll
        for (int j = 0; j < 4; j++) o[dn][j] = 0.f;
    float m0 = -1e30f, m1 = -1e30f, l0 = 0.f, l1 = 0.f;

    const int qrow0 = qbase + wid * 16 + g;
    const int qrow1 = qrow0 + 8;
    const int ktn = 2 * qt + 2;

    for (int kt = 0; kt < ktn; ++kt) {
        const int kbase = kt * 64;
        // ---- stage K (B-layout: n=key, k=d) and V (B-layout: n=d, k=key) ----
#pragma unroll
        for (int i = 0; i < 8; i++) {
            int idx = tid + i * 256;          // 2048 float4s
            int row = idx >> 5, k4 = idx & 31;
            const float* src = &qkv[(size_t)(rowbase + kbase + row) * QKV_N];
            float4 kv = *(const float4*)(src + kcol + k4 * 4);
            float4 vv = *(const float4*)(src + vcol + k4 * 4);
            {   // K: element (n=row, k=4*k4+j)
                int ks = k4 >> 1, khalf = k4 & 1;
                float* p = Kb + ((row >> 3) * 16 + ks) * BBLK + (row & 7) * 8 + khalf;
                p[0] = to_tf32(kv.x);
                p[2] = to_tf32(kv.y);
                p[4] = to_tf32(kv.z);
                p[6] = to_tf32(kv.w);
            }
            {   // V: element (n=4*k4+j, k=row)
                int nt = k4 >> 1;             // (4*k4)>>3
                int nb = (k4 & 1) * 4;        // (4*k4+j)&7 = nb + j
                float* p = Vb + (nt * 8 + (row >> 3)) * BBLK
                              + nb * 8 + (row & 3) * 2 + ((row >> 2) & 1);
                p[0]  = to_tf32(vv.x);
                p[8]  = to_tf32(vv.y);
                p[16] = to_tf32(vv.z);
                p[24] = to_tf32(vv.w);
            }
        }
        __syncthreads();

        // ---- S = Q @ K^T  (warp: 16 q-rows x 64 keys) ----
        float s[8][4];
#pragma unroll
        for (int nt = 0; nt < 8; nt++)
#pragma unroll
            for (int j = 0; j < 4; j++) s[nt][j] = 0.f;

#pragma unroll
        for (int kk = 0; kk < 16; ++kk) {
            uint32_t af[4];
            uint32_t aaddr = qa_u + (uint32_t)(((wid * 16 + kk) * ABLK + lane * 4) * 4);
            asm volatile("ld.shared.v4.b32 {%0,%1,%2,%3}, [%4];"
                         : "=r"(af[0]), "=r"(af[1]), "=r"(af[2]), "=r"(af[3])
                         : "r"(aaddr));
#pragma unroll
            for (int nt = 0; nt < 8; nt++) {
                uint32_t bf[2];
                uint32_t baddr = kb_u + (uint32_t)(((nt * 16 + kk) * BBLK + lane * 2) * 4);
                asm volatile("ld.shared.v2.b32 {%0,%1}, [%2];"
                             : "=r"(bf[0]), "=r"(bf[1]) : "r"(baddr));
                MMA_TF32(s[nt][0], s[nt][1], s[nt][2], s[nt][3],
                         af[0], af[1], af[2], af[3], bf[0], bf[1]);
            }
        }

        // ---- online softmax on S fragments ----
        const bool domask = (kt >= 2 * qt);
        float vmax0 = -1e30f, vmax1 = -1e30f;
#pragma unroll
        for (int nt = 0; nt < 8; nt++) {
            int c = kbase + nt * 8 + t * 2;
            float v0 = s[nt][0] * ATT_SCALE, v1 = s[nt][1] * ATT_SCALE;
            float v2 = s[nt][2] * ATT_SCALE, v3 = s[nt][3] * ATT_SCALE;
            if (domask) {
                if (c > qrow0)     v0 = -1e30f;
                if (c + 1 > qrow0) v1 = -1e30f;
                if (c > qrow1)     v2 = -1e30f;
                if (c + 1 > qrow1) v3 = -1e30f;
            }
            s[nt][0] = v0; s[nt][1] = v1; s[nt][2] = v2; s[nt][3] = v3;
            vmax0 = fmaxf(vmax0, fmaxf(v0, v1));
            vmax1 = fmaxf(vmax1, fmaxf(v2, v3));
        }
        vmax0 = fmaxf(vmax0, __shfl_xor_sync(0xffffffffu, vmax0, 1));
        vmax0 = fmaxf(vmax0, __shfl_xor_sync(0xffffffffu, vmax0, 2));
        vmax1 = fmaxf(vmax1, __shfl_xor_sync(0xffffffffu, vmax1, 1));
        vmax1 = fmaxf(vmax1, __shfl_xor_sync(0xffffffffu, vmax1, 2));

        float m0n = fmaxf(m0, vmax0), m1n = fmaxf(m1, vmax1);
        float a0 = __expf(m0 - m0n), a1 = __expf(m1 - m1n);
        float sum0 = 0.f, sum1 = 0.f;

        // P store offsets within an A block (local cols 2t and 2t+1)
        const int offA = 4 * ((2 * t) & 3) + 2 * (((2 * t) >> 2) & 1);
        const int offB = 4 * ((2 * t + 1) & 3) + 2 * (((2 * t + 1) >> 2) & 1);
#pragma unroll
        for (int nt = 0; nt < 8; nt++) {
            float p0 = __expf(s[nt][0] - m0n);
            float p1 = __expf(s[nt][1] - m0n);
            float p2 = __expf(s[nt][2] - m1n);
            float p3 = __expf(s[nt][3] - m1n);
            sum0 += p0 + p1;
            sum1 += p2 + p3;
            float* base = Pa + (wid * 8 + nt) * ABLK + 16 * g;
            base[offA]     = to_tf32(p0);
            base[offB]     = to_tf32(p1);
            base[offA + 1] = to_tf32(p2);
            base[offB + 1] = to_tf32(p3);
        }
        sum0 += __shfl_xor_sync(0xffffffffu, sum0, 1);
        sum0 += __shfl_xor_sync(0xffffffffu, sum0, 2);
        sum1 += __shfl_xor_sync(0xffffffffu, sum1, 1);
        sum1 += __shfl_xor_sync(0xffffffffu, sum1, 2);

        m0 = m0n; m1 = m1n;
        l0 = l0 * a0 + sum0;
        l1 = l1 * a1 + sum1;
#pragma unroll
        for (int dn = 0; dn < 16; dn++) {
            o[dn][0] *= a0; o[dn][1] *= a0;
            o[dn][2] *= a1; o[dn][3] *= a1;
        }
        __syncwarp();

        // ---- O += P @ V  (warp: 16 q-rows x 128 d) ----
#pragma unroll
        for (int kk = 0; kk < 8; ++kk) {
            uint32_t af[4];
            uint32_t aaddr = pa_u + (uint32_t)(((wid * 8 + kk) * ABLK + lane * 4) * 4);
            asm volatile("ld.shared.v4.b32 {%0,%1,%2,%3}, [%4];"
                         : "=r"(af[0]), "=r"(af[1]), "=r"(af[2]), "=r"(af[3])
                         : "r"(aaddr));
#pragma unroll
            for (int dn = 0; dn < 16; dn++) {
                uint32_t bf[2];
                uint32_t baddr = vb_u + (uint32_t)(((dn * 8 + kk) * BBLK + lane * 2) * 4);
                asm volatile("ld.shared.v2.b32 {%0,%1}, [%2];"
                             : "=r"(bf[0]), "=r"(bf[1]) : "r"(baddr));
                MMA_TF32(o[dn][0], o[dn][1], o[dn][2], o[dn][3],
                         af[0], af[1], af[2], af[3], bf[0], bf[1]);
            }
        }
        __syncthreads();
    }

    // ---- epilogue: O /= l, write ctx ----
    const float il0 = 1.f / l0, il1 = 1.f / l1;
    const int row0 = rowbase + qrow0;
#pragma unroll
    for (int dn = 0; dn < 16; dn++) {
        const int col = h * DH + dn * 8 + t * 2;
        *(float2*)&ctx[(size_t)row0 * CTX_N + col] =
            make_float2(o[dn][0] * il0, o[dn][1] * il0);
        *(float2*)&ctx[(size_t)(row0 + 8) * CTX_N + col] =
            make_float2(o[dn][2] * il1, o[dn][3] * il1);
    }
}

// ---------------------------------------------------------------------------
extern "C" void kernel_launch(void* const* d_in, const int* in_sizes, int n_in,
                              void* d_out, int out_size) {
    const float* hidden = (const float*)d_in[0];   // [B,S,HID]
    const float* cosT   = (const float*)d_in[1];   // [1,S,1,D]
    const float* sinT   = (const float*)d_in[2];
    const float* w_qkv  = (const float*)d_in[3];   // [HID, 5120]
    const float* qw     = (const float*)d_in[4];   // [128]
    const float* kw     = (const float*)d_in[5];   // [128]
    const float* w_o    = (const float*)d_in[6];   // [4096, HID]
    float* out = (float*)d_out;                    // [B,S,HID]

    float *qkv, *ctx, *wqkvT, *woT;
    cudaGetSymbolAddress((void**)&qkv,   g_qkv);
    cudaGetSymbolAddress((void**)&ctx,   g_ctx);
    cudaGetSymbolAddress((void**)&wqkvT, g_wqkvT);
    cudaGetSymbolAddress((void**)&woT,   g_woT);

    cudaFuncSetAttribute(gemm_mma, cudaFuncAttributeMaxDynamicSharedMemorySize,
                         GM_SMEM_BYTES);
    cudaFuncSetAttribute(attn_tc, cudaFuncAttributeMaxDynamicSharedMemorySize,
                         AT_SMEM_BYTES);

    // 0) Weight transposes to [N,K] for K-major B operand
    transpose32<<<dim3(QKV_N / 32, HID / 32), 256>>>(w_qkv, wqkvT, HID, QKV_N);
    transpose32<<<dim3(HID / 32, CTX_N / 32), 256>>>(w_o, woT, CTX_N, HID);

    // 1) QKV projection (mma.sync tf32): [2048,2048] @ [2048,5120]
    gemm_mma<<<dim3(NTOK / 128, QKV_N / 128), 256, GM_SMEM_BYTES>>>(
        hidden, wqkvT, qkv, NTOK, QKV_N, HID);

    // 2) RMSNorm + RoPE on q and k heads (in place)
    normrope_kernel<<<dim3(NTOK, NH + NKV), 128>>>(qkv, qw, kw, cosT, sinT);

    // 3) Causal GQA flash attention (mma.sync tf32)
    attn_tc<<<dim3(SS / 128, NH, BB), 256, AT_SMEM_BYTES>>>(qkv, ctx);

    // 4) Output projection (mma.sync tf32): [2048,4096] @ [4096,2048]
    gemm_mma<<<dim3(NTOK / 128, HID / 128), 256, GM_SMEM_BYTES>>>(
        ctx, woT, out, NTOK, HID, CTX_N);
}